// round 6
// baseline (speedup 1.0000x reference)
#include <cuda_runtime.h>
#include <math.h>
#include <stdint.h>

#define BZ   8
#define IM   128
#define HW   (IM * IM)          // 16384
#define CIN  3

// dft_gemm dynamic smem layout (bytes):
//   [0,      65536)  sW4  : float4[32*128]  swizzled W
//   [65536,  67584)  sRe  : float[4][128]
//   [67584,  69632)  sIm  : float[4][128]
//   [69632,  71680)  sS   : float[4][128]
//   [71680,  72192)  t128c: float[128]
//   [72192,  72704)  t128s: float[128]
//   [72704,  72832)  t32c : float[32]
//   [72832,  72960)  t32s : float[32]
#define SMEM_BYTES_DFT 72960
#define SMEM_BYTES_BC  65536      // 64KB replicated output tile

// Scratch: E[b][o][w] = leakyrelu(W @ S)
__device__ float g_E[BZ * IM * IM];

__device__ __forceinline__ uint32_t smem_u32(const void* p) {
    uint32_t a;
    asm("{ .reg .u64 t; cvta.to.shared.u64 t, %1; cvt.u32.u64 %0, t; }"
        : "=r"(a) : "l"(p));
    return a;
}

// ---------------------------------------------------------------------------
// K1: fused radix-4 column DFT magnitude + 1x1-conv GEMM + LeakyReLU.
// grid = (32 col-groups, 8 b), block = 128 threads = 4 warps = 4 columns.
// ---------------------------------------------------------------------------
__global__ void __launch_bounds__(128) dft_gemm_kernel(const float* __restrict__ x,
                                                       const float* __restrict__ conv_w) {
    extern __shared__ char smem[];
    float4* sW4   = (float4*)(smem);
    float (*sRe)[IM] = (float (*)[IM])(smem + 65536);
    float (*sIm)[IM] = (float (*)[IM])(smem + 67584);
    float (*sS )[IM] = (float (*)[IM])(smem + 69632);
    float* t128c = (float*)(smem + 71680);
    float* t128s = (float*)(smem + 72192);
    float* t32c  = (float*)(smem + 72704);
    float* t32s  = (float*)(smem + 72832);

    const int b    = blockIdx.y;
    const int w0   = blockIdx.x * 4;
    const int tid  = threadIdx.x;
    const int wl   = tid >> 5;
    const int lane = tid & 31;

    // Stage W: coalesced loads, swizzled stores.  o = row, j = float4-in-row.
    const float4* W4 = (const float4*)conv_w;
#pragma unroll
    for (int it = 0; it < 32; it++) {
        int idx = tid + 128 * it;                      // 0..4095
        int o = idx >> 5, j = idx & 31;
        sW4[j * IM + (j ^ o)] = W4[o * 32 + j];
    }

    // Load 4 columns (both channels) as float4 rows.
    const float* xb = x + (size_t)b * CIN * HW;
    for (int k = tid; k < 256; k += 128) {
        int ch = k >> 7, h = k & 127;
        float4 v = ((const float4*)(xb + (size_t)ch * HW))[h * (IM / 4) + (w0 >> 2)];
        float (*dst)[IM] = ch ? sIm : sRe;
        dst[0][h] = v.x; dst[1][h] = v.y; dst[2][h] = v.z; dst[3][h] = v.w;
    }

    // Twiddle tables (exact, one sincosf per thread).
    {
        float s, c;
        sincosf(-6.283185307179586f * (float)tid * (1.0f / 128.0f), &s, &c);
        t128c[tid] = c; t128s[tid] = s;
        if (tid < 32) {
            sincosf(-6.283185307179586f * (float)tid * (1.0f / 32.0f), &s, &c);
            t32c[tid] = c; t32s[tid] = s;
        }
    }
    __syncthreads();

    // Radix-4 DFT: 4 phase accumulators, table twiddles.
    float A0r = 0, A0i = 0, A1r = 0, A1i = 0, A2r = 0, A2i = 0, A3r = 0, A3i = 0;
    const float4* r4 = (const float4*)sRe[wl];
    const float4* m4 = (const float4*)sIm[wl];

#pragma unroll
    for (int t = 0; t < 32; t++) {
        int   k = (lane * t) & 31;
        float c = t32c[k], s = t32s[k];
        float4 xr = r4[t];
        float4 xm = m4[t];
        A0r = fmaf(xr.x, c, A0r); A0r = fmaf(-xm.x, s, A0r);
        A0i = fmaf(xr.x, s, A0i); A0i = fmaf( xm.x, c, A0i);
        A1r = fmaf(xr.y, c, A1r); A1r = fmaf(-xm.y, s, A1r);
        A1i = fmaf(xr.y, s, A1i); A1i = fmaf( xm.y, c, A1i);
        A2r = fmaf(xr.z, c, A2r); A2r = fmaf(-xm.z, s, A2r);
        A2i = fmaf(xr.z, s, A2i); A2i = fmaf( xm.z, c, A2i);
        A3r = fmaf(xr.w, c, A3r); A3r = fmaf(-xm.w, s, A3r);
        A3i = fmaf(xr.w, s, A3i); A3i = fmaf( xm.w, c, A3i);
    }

    // Final twiddles W^lane, W^2lane, W^3lane (exact table reads).
    float cw = t128c[lane],             sw = t128s[lane];
    float c2 = t128c[(2 * lane) & 127], s2 = t128s[(2 * lane) & 127];
    float c3 = t128c[(3 * lane) & 127], s3 = t128s[(3 * lane) & 127];

    float T0r = A0r,                 T0i = A0i;
    float T1r = cw * A1r - sw * A1i, T1i = cw * A1i + sw * A1r;
    float T2r = c2 * A2r - s2 * A2i, T2i = c2 * A2i + s2 * A2r;
    float T3r = c3 * A3r - s3 * A3i, T3i = c3 * A3i + s3 * A3r;

    float Er = T0r + T2r, Ei = T0i + T2i;
    float Fr = T1r + T3r, Fi = T1i + T3i;
    float Gr = T0r - T2r, Gi = T0i - T2i;
    float Hr = T1r - T3r, Hi = T1i - T3i;

    float m0r = Er + Fr, m0i = Ei + Fi;
    float m2r = Er - Fr, m2i = Ei - Fi;
    float m1r = Gr + Hi, m1i = Gi - Hr;
    float m3r = Gr - Hi, m3i = Gi + Hr;

    const float inv = 1.0f / 128.0f;
    sS[wl][lane     ] = sqrtf(m0r * m0r + m0i * m0i) * inv;
    sS[wl][lane + 32] = sqrtf(m1r * m1r + m1i * m1i) * inv;
    sS[wl][lane + 64] = sqrtf(m2r * m2r + m2i * m2i) * inv;
    sS[wl][lane + 96] = sqrtf(m3r * m3r + m3i * m3i) * inv;
    __syncthreads();

    // GEMM: thread t = output channel o; 4 w-accumulators.
    float a0 = 0, a1 = 0, a2 = 0, a3 = 0;
    const float4* q0 = (const float4*)sS[0];
    const float4* q1 = (const float4*)sS[1];
    const float4* q2 = (const float4*)sS[2];
    const float4* q3 = (const float4*)sS[3];

#pragma unroll 8
    for (int i4 = 0; i4 < 32; i4++) {
        float4 wv = sW4[i4 * IM + (i4 ^ tid)];         // conflict-free swizzled read
        float4 v0 = q0[i4], v1 = q1[i4], v2 = q2[i4], v3 = q3[i4];
        a0 = fmaf(wv.x, v0.x, a0); a0 = fmaf(wv.y, v0.y, a0);
        a0 = fmaf(wv.z, v0.z, a0); a0 = fmaf(wv.w, v0.w, a0);
        a1 = fmaf(wv.x, v1.x, a1); a1 = fmaf(wv.y, v1.y, a1);
        a1 = fmaf(wv.z, v1.z, a1); a1 = fmaf(wv.w, v1.w, a1);
        a2 = fmaf(wv.x, v2.x, a2); a2 = fmaf(wv.y, v2.y, a2);
        a2 = fmaf(wv.z, v2.z, a2); a2 = fmaf(wv.w, v2.w, a2);
        a3 = fmaf(wv.x, v3.x, a3); a3 = fmaf(wv.y, v3.y, a3);
        a3 = fmaf(wv.z, v3.z, a3); a3 = fmaf(wv.w, v3.w, a3);
    }

    float4 e;
    e.x = (a0 >= 0.0f) ? a0 : 0.2f * a0;
    e.y = (a1 >= 0.0f) ? a1 : 0.2f * a1;
    e.z = (a2 >= 0.0f) ? a2 : 0.2f * a2;
    e.w = (a3 >= 0.0f) ? a3 : 0.2f * a3;
    *(float4*)(g_E + (size_t)(b * IM + tid) * IM + w0) = e;
}

// ---------------------------------------------------------------------------
// K2: broadcast E over h into out via TMA bulk store; o==128 copies x ch 2.
// grid = (129 o, 8 b), block = 256 threads, 64KB dynamic smem.
// ---------------------------------------------------------------------------
__global__ void __launch_bounds__(256) bcast_kernel(const float* __restrict__ x,
                                                    float* __restrict__ out) {
    extern __shared__ char smem[];
    const int o   = blockIdx.x;    // 0..128
    const int b   = blockIdx.y;
    const int tid = threadIdx.x;

    float* dst = out + (size_t)(b * (IM + 1) + o) * HW;

    if (o == IM) {
        // passthrough channel: plain copy (0.5 MB total across 8 blocks)
        float4*       d4  = (float4*)dst;
        const float4* src = (const float4*)(x + (size_t)b * CIN * HW + 2 * HW);
#pragma unroll
        for (int j = tid; j < HW / 4; j += 256) d4[j] = src[j];
        return;
    }

    // Replicate E row (512B) into 64KB smem tile.
    const float4* e4 = (const float4*)(g_E + (size_t)(b * IM + o) * IM);
    float4 v = e4[tid & 31];
    float4* s4 = (float4*)smem;
    const int w4 = tid & 31;
    const int h0 = tid >> 5;           // 0..7
#pragma unroll
    for (int h = h0; h < IM; h += 8) s4[h * (IM / 4) + w4] = v;

    __syncthreads();
    asm volatile("fence.proxy.async.shared::cta;" ::: "memory");

    if (tid == 0) {
        uint32_t saddr = smem_u32(smem);
        asm volatile(
            "cp.async.bulk.global.shared::cta.bulk_group [%0], [%1], %2;"
            :: "l"((unsigned long long)dst), "r"(saddr), "r"(HW * 4)
            : "memory");
        asm volatile("cp.async.bulk.commit_group;" ::: "memory");
        asm volatile("cp.async.bulk.wait_group 0;" ::: "memory");
    }
}

// ---------------------------------------------------------------------------
extern "C" void kernel_launch(void* const* d_in, const int* in_sizes, int n_in,
                              void* d_out, int out_size) {
    const float* x      = (const float*)d_in[0];
    const float* conv_w = (const float*)d_in[2];
    float*       out    = (float*)d_out;

    cudaFuncSetAttribute(dft_gemm_kernel,
                         cudaFuncAttributeMaxDynamicSharedMemorySize, SMEM_BYTES_DFT);
    cudaFuncSetAttribute(bcast_kernel,
                         cudaFuncAttributeMaxDynamicSharedMemorySize, SMEM_BYTES_BC);

    dft_gemm_kernel<<<dim3(IM / 4, BZ), 128, SMEM_BYTES_DFT>>>(x, conv_w);
    bcast_kernel<<<dim3(IM + 1, BZ), 256, SMEM_BYTES_BC>>>(x, out);
}